// round 5
// baseline (speedup 1.0000x reference)
#include <cuda_runtime.h>
#include <math.h>

#define BB 8
#define CC 256
#define DD 128
#define KK 1024
#define NNN 4096
#define GAMMA 0.99f
#define OMG 0.01f

#define OUT_NUM (BB*DD*NNN)          /* 4194304 */
#define OUT_DEN (OUT_NUM + KK*DD)    /* 4325376 */

#define EPITCH 132

__device__ __align__(128) float g_ze[BB*DD*NNN];
__device__ float g_qsq[KK];
__device__ float g_qs[KK];

// -------- swizzled transposed ze tile addressing: [n][d], 128 floats/row ----
__device__ __forceinline__ int zt_off4(int n, int d4) {
    return (n << 7) + (((d4 & 24) | ((d4 ^ n) & 7)) << 2);
}
__device__ __forceinline__ int zt_off(int n, int d) {
    return zt_off4(n, d >> 2) + (d & 3);
}

// ============================================================================
// prep: codebook norms + EMA output initialization (out = gamma * ema)
// ============================================================================
__global__ void prep_kernel(const float* __restrict__ emb,
                            const float* __restrict__ ema_numer,
                            const float* __restrict__ ema_denom,
                            float* __restrict__ out) {
    int idx = blockIdx.x * blockDim.x + threadIdx.x;
    if (idx < KK * DD) out[OUT_NUM + idx] = GAMMA * ema_numer[idx];
    if (idx < KK) {
        out[OUT_DEN + idx] = GAMMA * ema_denom[idx];
        const float4* row = reinterpret_cast<const float4*>(emb + idx * DD);
        float s = 0.f;
#pragma unroll
        for (int i = 0; i < DD / 4; ++i) {
            float4 v = row[i];
            s += v.x * v.x + v.y * v.y + v.z * v.z + v.w * v.w;
        }
        g_qsq[idx] = s;
        g_qs[idx]  = sqrtf(s);
    }
}

// ============================================================================
// ze = W_lin @ z  per batch:  (128 x 256) @ (256 x 4096) -> g_ze
// block: 256 threads, tile 128d x 128n, 8x8 micro-tiles
// ============================================================================
__global__ void __launch_bounds__(256, 1)
ze_kernel(const float* __restrict__ z, const float* __restrict__ W) {
    extern __shared__ float sm[];
    float* sW = sm;             // [c][d]  256*128
    float* sZ = sm + 256 * 128; // [cc][n] 32*128
    int tid = threadIdx.x;
    int tx = tid & 15, ty = tid >> 4;
    int n0 = blockIdx.x * 128, b = blockIdx.y;

    // load W transposed into smem: sW[c*128 + d]
    for (int t = 0; t < 32; ++t) {
        int v = tid + t * 256;            // float4 id (8192 total)
        int d = v >> 6, c4 = (v & 63) << 2;
        float4 w = *reinterpret_cast<const float4*>(W + d * CC + c4);
        sW[(c4 + 0) * 128 + d] = w.x;
        sW[(c4 + 1) * 128 + d] = w.y;
        sW[(c4 + 2) * 128 + d] = w.z;
        sW[(c4 + 3) * 128 + d] = w.w;
    }

    float acc[8][8];
#pragma unroll
    for (int i = 0; i < 8; ++i)
#pragma unroll
        for (int j = 0; j < 8; ++j) acc[i][j] = 0.f;

    const float* zb = z + (size_t)b * CC * NNN + n0;
    for (int cc0 = 0; cc0 < CC; cc0 += 32) {
        __syncthreads();
#pragma unroll
        for (int t = 0; t < 4; ++t) {
            int v = tid + t * 256;        // 1024 float4
            int r = v >> 5, c4 = (v & 31) << 2;
            *reinterpret_cast<float4*>(sZ + r * 128 + c4) =
                *reinterpret_cast<const float4*>(zb + (size_t)(cc0 + r) * NNN + c4);
        }
        __syncthreads();
#pragma unroll 4
        for (int cc = 0; cc < 32; ++cc) {
            float wv[8], zv[8];
#pragma unroll
            for (int i = 0; i < 8; ++i) wv[i] = sW[(cc0 + cc) * 128 + i * 16 + ty];
#pragma unroll
            for (int j = 0; j < 8; ++j) zv[j] = sZ[cc * 128 + j * 16 + tx];
#pragma unroll
            for (int i = 0; i < 8; ++i)
#pragma unroll
                for (int j = 0; j < 8; ++j) acc[i][j] += wv[i] * zv[j];
        }
    }
    float* zo = g_ze + (size_t)b * DD * NNN + n0;
#pragma unroll
    for (int i = 0; i < 8; ++i)
#pragma unroll
        for (int j = 0; j < 8; ++j)
            zo[(i * 16 + ty) * NNN + j * 16 + tx] = acc[i][j];
}

// ============================================================================
// fused: dots = emb @ ze, scaled-L2 argmin over K, gather zq, EMA scatter-add
// block: 256 threads, tile = all K x 128 n for one b; 8x8 micro-tiles
// ============================================================================
__global__ void __launch_bounds__(256, 1)
vq_kernel(const float* __restrict__ emb, float* __restrict__ out) {
    extern __shared__ float sm[];
    float* s_zt   = sm;                   // swizzled ze^T tile  128*128
    float* s_emb  = sm + 16384;           // emb tile            128*EPITCH
    float* s_qsq  = s_emb + 128 * EPITCH; // 128
    float* s_qs   = s_qsq + 128;          // 128
    float* s_zesq = s_qs + 128;           // 128
    float* s_a    = s_zesq + 128;         // 128
    int*   s_idx  = (int*)(s_a + 128);    // 128

    int tid = threadIdx.x;
    int tx = tid & 15, ty = tid >> 4;
    int b = blockIdx.y, n0 = blockIdx.x * 128;
    const float* zeg = g_ze + (size_t)b * DD * NNN + n0;

    // ---- prologue: load ze tile, transpose + swizzle into smem ----
    for (int t = 0; t < 16; ++t) {
        int v = tid + t * 256;            // float4 id (4096 total)
        int d = v >> 5, n4 = (v & 31) << 2;
        float4 val = *reinterpret_cast<const float4*>(zeg + (size_t)d * NNN + n4);
        s_zt[zt_off(n4 + 0, d)] = val.x;
        s_zt[zt_off(n4 + 1, d)] = val.y;
        s_zt[zt_off(n4 + 2, d)] = val.z;
        s_zt[zt_off(n4 + 3, d)] = val.w;
    }
    __syncthreads();
    if (tid < 128) {
        float s = 0.f;
#pragma unroll
        for (int d4 = 0; d4 < 32; ++d4) {
            float4 v = *reinterpret_cast<float4*>(s_zt + zt_off4(tid, d4));
            s += v.x * v.x + v.y * v.y + v.z * v.z + v.w * v.w;
        }
        s_zesq[tid] = s;
        s_a[tid]    = sqrtf(s);
    }

    float bn[8], bd[8];
    int   bi[8];
#pragma unroll
    for (int j = 0; j < 8; ++j) { bn[j] = 1e30f; bd[j] = 1.f; bi[j] = 0; }

    // ---- mainloop over codebook tiles ----
    for (int kt = 0; kt < KK / 128; ++kt) {
        __syncthreads();   // previous tile consumed (also guards zesq on kt==0)
        const float* eg = emb + kt * 128 * DD;
        for (int t = 0; t < 16; ++t) {
            int v = tid + t * 256;
            int r = v >> 5, c4 = (v & 31) << 2;
            *reinterpret_cast<float4*>(s_emb + r * EPITCH + c4) =
                *reinterpret_cast<const float4*>(eg + r * DD + c4);
        }
        if (tid < 128) {
            s_qsq[tid] = g_qsq[kt * 128 + tid];
            s_qs[tid]  = g_qs[kt * 128 + tid];
        }
        __syncthreads();

        float acc[8][8];
#pragma unroll
        for (int i = 0; i < 8; ++i)
#pragma unroll
            for (int j = 0; j < 8; ++j) acc[i][j] = 0.f;

#pragma unroll 2
        for (int d4 = 0; d4 < 32; ++d4) {
            float4 ev[8], zv[8];
#pragma unroll
            for (int i = 0; i < 8; ++i)
                ev[i] = *reinterpret_cast<float4*>(s_emb + (i * 16 + ty) * EPITCH + (d4 << 2));
#pragma unroll
            for (int j = 0; j < 8; ++j)
                zv[j] = *reinterpret_cast<float4*>(s_zt + zt_off4(j * 16 + tx, d4));
#pragma unroll
            for (int i = 0; i < 8; ++i)
#pragma unroll
                for (int j = 0; j < 8; ++j) {
                    acc[i][j] += ev[i].x * zv[j].x;
                    acc[i][j] += ev[i].y * zv[j].y;
                    acc[i][j] += ev[i].z * zv[j].z;
                    acc[i][j] += ev[i].w * zv[j].w;
                }
        }

        // argmin update: minimize num/den^2 via cross-multiplied compare
#pragma unroll
        for (int i = 0; i < 8; ++i) {
            int kk = i * 16 + ty;
            float qsq = s_qsq[kk], qs = s_qs[kk];
            int kg = kt * 128 + kk;
#pragma unroll
            for (int j = 0; j < 8; ++j) {
                int n = j * 16 + tx;
                float num = fmaxf(s_zesq[n] + qsq - 2.f * acc[i][j], 0.f);
                float den = s_a[n] + qs;
                float d2  = den * den;
                if (num * bd[j] < bn[j] * d2) { bn[j] = num; bd[j] = d2; bi[j] = kg; }
            }
        }
    }
    __syncthreads();

    // ---- cross-thread argmin reduction (overlay on s_emb) ----
    float* rn = s_emb;
    float* rd = s_emb + 2048;
    int*   ri = (int*)(s_emb + 4096);
#pragma unroll
    for (int j = 0; j < 8; ++j) {
        int n = j * 16 + tx;
        rn[ty * 128 + n] = bn[j];
        rd[ty * 128 + n] = bd[j];
        ri[ty * 128 + n] = bi[j];
    }
    __syncthreads();
    if (tid < 128) {
        float Bn = rn[tid], Bd = rd[tid];
        int Bi = ri[tid];
        for (int r = 1; r < 16; ++r) {
            float cn = rn[r * 128 + tid], cd = rd[r * 128 + tid];
            int ci = ri[r * 128 + tid];
            float lhs = cn * Bd, rhs = Bn * cd;
            if (lhs < rhs || (lhs == rhs && ci < Bi)) { Bn = cn; Bd = cd; Bi = ci; }
        }
        s_idx[tid] = Bi;
        atomicAdd(out + OUT_DEN + Bi, OMG);
    }
    __syncthreads();

    // ---- gather codebook rows (stage in smem) + EMA numer scatter-add ----
    float* s_g = s_emb;  // reuse, pitch EPITCH, [n][d]
    float* out_num = out + OUT_NUM;
    for (int t = 0; t < 16; ++t) {
        int v = tid + t * 256;           // float4 id
        int n = v >> 5, d4 = v & 31;
        int idx = s_idx[n];
        float4 ev = *reinterpret_cast<const float4*>(emb + idx * DD + (d4 << 2));
        *reinterpret_cast<float4*>(s_g + n * EPITCH + (d4 << 2)) = ev;
        float4 zv = *reinterpret_cast<float4*>(s_zt + zt_off4(n, d4));
        float* dst = out_num + idx * DD + (d4 << 2);
        atomicAdd(dst + 0, OMG * zv.x);
        atomicAdd(dst + 1, OMG * zv.y);
        atomicAdd(dst + 2, OMG * zv.z);
        atomicAdd(dst + 3, OMG * zv.w);
    }
    __syncthreads();

    // ---- write zq (coalesced float4 over n) ----
    float* out_zq = out + (size_t)b * DD * NNN + n0;
    for (int t = 0; t < 16; ++t) {
        int v = tid + t * 256;
        int d = v >> 5, n4 = (v & 31) << 2;
        float4 q;
        q.x = s_g[(n4 + 0) * EPITCH + d];
        q.y = s_g[(n4 + 1) * EPITCH + d];
        q.z = s_g[(n4 + 2) * EPITCH + d];
        q.w = s_g[(n4 + 3) * EPITCH + d];
        *reinterpret_cast<float4*>(out_zq + (size_t)d * NNN + n4) = q;
    }
}

// ============================================================================
extern "C" void kernel_launch(void* const* d_in, const int* in_sizes, int n_in,
                              void* d_out, int out_size) {
    const float* z         = (const float*)d_in[0];
    const float* W_lin     = (const float*)d_in[1];
    const float* emb       = (const float*)d_in[2];
    const float* ema_numer = (const float*)d_in[3];
    const float* ema_denom = (const float*)d_in[4];
    float* out = (float*)d_out;

    const int ZE_SMEM = (256 * 128 + 32 * 128) * 4;              // 147456
    const int VQ_SMEM = (16384 + 128 * EPITCH + 4 * 128 + 128) * 4; // 135680

    cudaFuncSetAttribute(ze_kernel, cudaFuncAttributeMaxDynamicSharedMemorySize, ZE_SMEM);
    cudaFuncSetAttribute(vq_kernel, cudaFuncAttributeMaxDynamicSharedMemorySize, VQ_SMEM);

    prep_kernel<<<(KK * DD + 255) / 256, 256>>>(emb, ema_numer, ema_denom, out);
    ze_kernel<<<dim3(NNN / 128, BB), 256, ZE_SMEM>>>(z, W_lin);
    vq_kernel<<<dim3(NNN / 128, BB), 256, VQ_SMEM>>>(emb, out);
}